// round 16
// baseline (speedup 1.0000x reference)
#include <cuda_runtime.h>
#include <cuda_bf16.h>
#include <math.h>
#include <stdint.h>

// ---------------- problem constants ----------------
#define Bq   2
#define Lq   4096
#define DIMq 512
#define Hq   4
#define DHq  128
#define Cq   64
#define Nq   64          // L / C
#define BHq  8           // B * H
#define NCHUNK 512       // BH * N
#define MAXLR 0.01f
#define EPSq  1e-6f

// ---------------- scratch (device globals; allocation-free) ----------------
// buffers marked (tf32) hold fp32 values pre-rounded to tf32.
__device__ float d_s_norm[Bq*Lq*DIMq];       // (tf32)
__device__ float d_r_norm[Bq*Lq*DIMq];       // (tf32)
__device__ float d_keys  [BHq*Lq*DHq];       // (tf32)
__device__ float d_vals  [BHq*Lq*DHq];       // fp32
__device__ float d_quer  [BHq*Lq*DHq];       // (tf32)
__device__ float d_lr    [BHq*Lq];
__device__ float d_am    [BHq*Nq];
__device__ float d_dc    [BHq*Nq];
__device__ float d_g0    [NCHUNK*DHq*DHq];   // fp32, TRANSPOSED layout
__device__ float d_g1    [NCHUNK*DHq*DHq];   // fp32, TRANSPOSED layout
__device__ float d_w0t   [NCHUNK*DHq*DHq];   // (tf32), TRANSPOSED layout
__device__ float d_w1t   [NCHUNK*DHq*DHq];   // (tf32), TRANSPOSED layout
__device__ float d_comb  [Bq*Lq*DIMq];       // (tf32)
__device__ float d_gatev [Bq*Lq*Hq];
// pretransposed weights, (tf32)
__device__ float d_wkvT[2*Hq*DHq*DIMq];
__device__ float d_wqT [Hq*DHq*DIMq];
__device__ float d_wcT [DIMq*Hq*DHq];
__device__ float d_w0T [DHq*DHq];
__device__ float d_w1T [DHq*DHq];

__device__ __forceinline__ float sigm(float x){ return 1.f/(1.f+expf(-x)); }

// ---------------- tf32 mma primitives ----------------
__device__ __forceinline__ uint32_t f2tf32(float x){
    uint32_t r; asm("cvt.rna.tf32.f32 %0, %1;" : "=r"(r) : "f"(x)); return r;
}
__device__ __forceinline__ float f2tf32f(float x){ return __uint_as_float(f2tf32(x)); }

__device__ __forceinline__ void mma8(float (&c)[4],
                                     uint32_t a0,uint32_t a1,uint32_t a2,uint32_t a3,
                                     uint32_t b0,uint32_t b1){
    asm volatile("mma.sync.aligned.m16n8k8.row.col.f32.tf32.tf32.f32 "
        "{%0,%1,%2,%3},{%4,%5,%6,%7},{%8,%9},{%0,%1,%2,%3};"
        : "+f"(c[0]),"+f"(c[1]),"+f"(c[2]),"+f"(c[3])
        : "r"(a0),"r"(a1),"r"(a2),"r"(a3),"r"(b0),"r"(b1));
}

__device__ __forceinline__ void ldsm4(uint32_t* r, uint32_t addr){
    asm volatile("ldmatrix.sync.aligned.m8n8.x4.shared.b16 {%0,%1,%2,%3}, [%4];"
        : "=r"(r[0]),"=r"(r[1]),"=r"(r[2]),"=r"(r[3]) : "r"(addr));
}

__device__ __forceinline__ uint32_t ldsmBase(uint32_t shAddr, int rbase, int ap, int lane){
    return shAddr + (uint32_t)(((rbase + (lane&15))*ap + ((lane>>4)<<2))*4);
}

// ---------------- cp.async helpers (.cg — bypass L1, data consumed once) ----------------
__device__ __forceinline__ void cpa16(uint32_t dst, const float* src){
    asm volatile("cp.async.cg.shared.global [%0],[%1],16;"::"r"(dst),"l"(src));
}
__device__ __forceinline__ void cpa16z(uint32_t dst, const float* src, bool p){
    int sz = p ? 16 : 0;
    asm volatile("cp.async.cg.shared.global [%0],[%1],16,%2;"::"r"(dst),"l"(src),"r"(sz));
}
__device__ __forceinline__ void cpcommit(){ asm volatile("cp.async.commit_group;"); }
template<int N> __device__ __forceinline__ void cpwait(){ asm volatile("cp.async.wait_group %0;"::"n"(N)); }

// both-side ldmatrix warp tile
template<int MT,int NT,int KS>
__device__ __forceinline__ void wtileLL(uint32_t aB,int ap,uint32_t bB,int bp,
                                        float (&acc)[MT][NT][4])
{
#pragma unroll
    for (int ks=0;ks<KS;ks++){
        int k0 = ks*8;
        uint32_t af[MT][4];
#pragma unroll
        for (int mt=0;mt<MT;mt++)
            ldsm4(af[mt], aB + (uint32_t)((mt*16*ap + k0)*4));
        uint32_t bq[NT/2][4];
#pragma unroll
        for (int nt2=0;nt2<NT/2;nt2++)
            ldsm4(bq[nt2], bB + (uint32_t)((nt2*16*bp + k0)*4));
#pragma unroll
        for (int mt=0;mt<MT;mt++)
#pragma unroll
            for (int nt=0;nt<NT;nt++)
                mma8(acc[mt][nt], af[mt][0],af[mt][1],af[mt][2],af[mt][3],
                     bq[nt>>1][nt&1], bq[nt>>1][2+(nt&1)]);
    }
}

// A ldmatrix, B scalar (k-major)
template<int MT,int NT,int KS>
__device__ __forceinline__ void wtileLS(uint32_t aB,int ap,const uint32_t* B,int bp,
                                        float (&acc)[MT][NT][4], int cbase, int lane)
{
    int g = lane>>2, tg = lane&3;
#pragma unroll
    for (int ks=0;ks<KS;ks++){
        int k0 = ks*8;
        uint32_t af[MT][4];
#pragma unroll
        for (int mt=0;mt<MT;mt++)
            ldsm4(af[mt], aB + (uint32_t)((mt*16*ap + k0)*4));
        uint32_t bf[NT][2];
#pragma unroll
        for (int nt=0;nt<NT;nt++){
            int n = cbase + nt*8 + g;
            bf[nt][0] = B[(k0+tg)*bp + n];
            bf[nt][1] = B[(k0+tg+4)*bp + n];
        }
#pragma unroll
        for (int mt=0;mt<MT;mt++)
#pragma unroll
            for (int nt=0;nt<NT;nt++)
                mma8(acc[mt][nt], af[mt][0],af[mt][1],af[mt][2],af[mt][3],
                     bf[nt][0],bf[nt][1]);
    }
}

// ---------------- merged transpose kernel (all 5 weights, tf32-rounded) ----------------
__global__ void __launch_bounds__(256) transpose_all(const float* __restrict__ w_kv,
                                                     const float* __restrict__ w_q,
                                                     const float* __restrict__ w_comb,
                                                     const float* __restrict__ w0,
                                                     const float* __restrict__ w1)
{
    __shared__ float t[32][33];
    int z = blockIdx.z;
    const float* in; float* out; int R, Cc;
    switch (z){
        case 0: in = w_kv;   out = d_wkvT; R = DIMq;   Cc = 2*Hq*DHq; break;
        case 1: in = w_q;    out = d_wqT;  R = DIMq;   Cc = Hq*DHq;   break;
        case 2: in = w_comb; out = d_wcT;  R = Hq*DHq; Cc = DIMq;     break;
        case 3: in = w0;     out = d_w0T;  R = DHq;    Cc = DHq;      break;
        default:in = w1;     out = d_w1T;  R = DHq;    Cc = DHq;      break;
    }
    int bx = blockIdx.x*32, by = blockIdx.y*32;
    if (bx >= Cc || by >= R) return;
#pragma unroll
    for (int i=0;i<4;i++)
        t[threadIdx.y + 8*i][threadIdx.x] = in[(size_t)(by + threadIdx.y + 8*i)*Cc + bx + threadIdx.x];
    __syncthreads();
#pragma unroll
    for (int i=0;i<4;i++)
        out[(size_t)(bx + threadIdx.y + 8*i)*R + by + threadIdx.x] = f2tf32f(t[threadIdx.x][threadIdx.y + 8*i]);
}

// ---------------- K1: per-token rmsnorm + fused lr/gate projections ----------------
__global__ void __launch_bounds__(128) norm_kernel(const float* __restrict__ seq,
                                                   const float* __restrict__ ss,
                                                   const float* __restrict__ rs,
                                                   const float* __restrict__ w_ada,
                                                   const float* __restrict__ w_gate)
{
    int token = blockIdx.x;              // b*L + t
    int tid = threadIdx.x;
    int lane = tid & 31, w = tid >> 5;
    const float* x = seq + (size_t)token*DIMq;
    float v[4]; float acc = 0.f;
#pragma unroll
    for (int i=0;i<4;i++){ v[i] = x[tid + 128*i]; acc += v[i]*v[i]; }
#pragma unroll
    for (int off=16;off;off>>=1) acc += __shfl_xor_sync(0xffffffffu, acc, off);
    __shared__ float red[4];
    __shared__ float red8[4][8];
    if (lane==0) red[w] = acc;
    __syncthreads();
    float tot = red[0]+red[1]+red[2]+red[3];
    float rms = rsqrtf(tot*(1.f/DIMq) + EPSq);
    float p[8] = {0,0,0,0,0,0,0,0};
#pragma unroll
    for (int i=0;i<4;i++){
        int d = tid + 128*i;
        float y = v[i]*rms;
        float ysv = y*ss[d], yrv = y*rs[d];
        d_s_norm[(size_t)token*DIMq + d] = f2tf32f(ysv);
        d_r_norm[(size_t)token*DIMq + d] = f2tf32f(yrv);
#pragma unroll
        for (int h=0;h<4;h++){
            p[h]   += ysv*w_ada [d*4+h];
            p[4+h] += yrv*w_gate[d*4+h];
        }
    }
#pragma unroll
    for (int h=0;h<8;h++)
#pragma unroll
        for (int off=16;off;off>>=1) p[h] += __shfl_xor_sync(0xffffffffu, p[h], off);
    if (lane==0)
#pragma unroll
        for (int h=0;h<8;h++) red8[w][h] = p[h];
    __syncthreads();
    if (tid < 8){
        float s = red8[0][tid]+red8[1][tid]+red8[2][tid]+red8[3][tid];
        int b = token >> 12, t = token & (Lq-1);
        if (tid < 4)
            d_lr[((size_t)(b*Hq+tid))*Lq + t] = sigm(s)*MAXLR;
        else if (t >= Cq-1)
            d_gatev[((size_t)b*Lq + (t-(Cq-1)))*Hq + (tid-4)] = sigm(s);
    }
}

// ---------------- fused chunk-mean + ada_mom/decay ----------------
__global__ void __launch_bounds__(512) cmeanmom_kernel(const float* __restrict__ wm,
                                                       const float* __restrict__ wd)
{
    __shared__ float redw[16][8];
    int bn = blockIdx.x;            // b*N + n
    int d = threadIdx.x;
    int lane = d & 31, w = d >> 5;
    int b = bn / Nq, n = bn % Nq;
    const float* base = d_s_norm + ((size_t)b*Lq + n*Cq)*DIMq + d;
    float acc = 0.f;
#pragma unroll 8
    for (int c=0;c<Cq;c++) acc += base[(size_t)c*DIMq];
    float mean = acc*(1.f/Cq);
    float p[8];
#pragma unroll
    for (int h=0;h<4;h++){
        p[h]   = mean*wm[d*4+h];
        p[4+h] = mean*wd[d*4+h];
    }
#pragma unroll
    for (int h=0;h<8;h++)
#pragma unroll
        for (int off=16;off;off>>=1) p[h] += __shfl_xor_sync(0xffffffffu, p[h], off);
    if (lane==0)
#pragma unroll
        for (int h=0;h<8;h++) redw[w][h] = p[h];
    __syncthreads();
    if (d < 8){
        float s = 0.f;
#pragma unroll
        for (int i=0;i<16;i++) s += redw[i][d];
        if (d < 4) d_am[(size_t)(b*Hq+d)*Nq + n]     = sigm(s);
        else       d_dc[(size_t)(b*Hq+d-4)*Nq + n]  = sigm(s);
    }
}

// ---------------- big GEMM, tf32 TC, 128x128 tiles, cp.async 3-stage ----------------
// MODE 0: keys/vals head-major; MODE 1: A shifted from r_norm, out queries; MODE 2: out shifted
#define GAP 36
#define GBP 36
#define GSTG (128*GAP + 128*GBP)
template<int MODE>
__global__ void __launch_bounds__(256,2) gemm_tc(const float* __restrict__ A,
                                                 const float* __restrict__ WT,
                                                 float* __restrict__ out0,
                                                 float* __restrict__ out1,
                                                 int K)
{
    extern __shared__ uint32_t sh[];
    uint32_t shAddr = (uint32_t)__cvta_generic_to_shared(sh);
    int tid = threadIdx.x, lane = tid & 31, wid = tid >> 5;
    int wm = wid >> 1, wn = wid & 1;       // 4 x 2 warps, 32x64 tiles
    int m0 = blockIdx.y*128, n0 = blockIdx.x*128;
    float acc[2][8][4] = {};
    int ar = tid>>3, ac4 = tid&7;          // rows ar+32i, 16B col ac4

    const int NK = K/32;
    auto issue = [&](int kt){
        int k0 = kt*32;
        uint32_t aB = shAddr + (uint32_t)((kt%3)*GSTG*4);
        uint32_t bB = aB + 128*GAP*4;
#pragma unroll
        for (int i=0;i<4;i++){
            int gr = m0 + ar + 32*i;
            uint32_t d = aB + (uint32_t)(((ar+32*i)*GAP + ac4*4)*4);
            if (MODE==1){
                int t = gr & (Lq-1);
                cpa16z(d, &A[(size_t)(gr+Cq-1)*K + k0 + ac4*4], t <= Lq-Cq);
            } else {
                cpa16(d, &A[(size_t)gr*K + k0 + ac4*4]);
            }
        }
#pragma unroll
        for (int i=0;i<4;i++)
            cpa16(bB + (uint32_t)(((ar+32*i)*GBP + ac4*4)*4),
                  &WT[(size_t)(n0 + ar + 32*i)*K + k0 + ac4*4]);
        cpcommit();
    };

    issue(0);
    if (NK>1) issue(1);
#pragma unroll 1
    for (int kt=0; kt<NK; kt++){
        if (kt == NK-1) cpwait<0>(); else cpwait<1>();
        __syncthreads();
        if (kt+2 < NK) issue(kt+2);
        uint32_t aB = shAddr + (uint32_t)((kt%3)*GSTG*4);
        uint32_t bB = aB + 128*GAP*4;
        wtileLL<2,8,4>(ldsmBase(aB, wm*32, GAP, lane), GAP,
                       ldsmBase(bB, wn*64, GBP, lane), GBP, acc);
    }

    int g = lane>>2, tg = lane&3;
#pragma unroll
    for (int mt=0;mt<2;mt++)
#pragma unroll
    for (int nt=0;nt<8;nt++)
#pragma unroll
    for (int eh=0;eh<2;eh++){
        int row = m0 + wm*32 + mt*16 + g + eh*8;
        int col = n0 + wn*64 + nt*8 + 2*tg;
        float va = acc[mt][nt][eh*2+0];
        float vb = acc[mt][nt][eh*2+1];
        int b = row >> 12, t = row & (Lq-1);
        if (MODE==0){
            if (col < Hq*DHq){
                int h = col>>7, d = col&127;
                *(float2*)&out0[((size_t)(b*Hq+h)*Lq + t)*DHq + d] =
                    make_float2(f2tf32f(va), f2tf32f(vb));
            } else {
                int c2 = col - Hq*DHq; int h = c2>>7, d = c2&127;
                *(float2*)&out1[((size_t)(b*Hq+h)*Lq + t)*DHq + d] = make_float2(va, vb);
            }
        } else if (MODE==1){
            int h = col>>7, d = col&127;
            *(float2*)&out0[((size_t)(b*Hq+h)*Lq + t)*DHq + d] =
                make_float2(f2tf32f(va), f2tf32f(vb));
        } else {
            if (t <= Lq - Cq)
                *(float2*)&out0[((size_t)b*Lq + t + Cq - 1)*DIMq + col] = make_float2(va, vb);
        }
    }
}

// ---------------- per-chunk kernels ----------------
#define PT  132
#define PXT 68   // pitch of 128x64 transposed tiles

// ---------------- chunk gradient (512 threads, 16 warps) ----------------
__global__ void __launch_bounds__(512) chunk_grad_kernel()
{
    extern __shared__ uint32_t smu[];
    uint32_t* Ks = smu;            // 64*PT keys (tf32)
    uint32_t* Ab = Ks + 64*PT;     // a=silu(h) (tf32)
    uint32_t* Db = Ab + 64*PT;     // v (fp32), later dpred (tf32) row-major
    uint32_t* XT = Db + 64*PT;     // 128*PXT: dpred^T, later dh^T (tf32)
    uint32_t* Ws = XT + 128*PXT;   // 128*PT weights (w0T, then w1T)
    float* Lr = (float*)(Ws + 128*PT);
    uint32_t KsA = (uint32_t)__cvta_generic_to_shared(Ks);
    uint32_t AbA = (uint32_t)__cvta_generic_to_shared(Ab);
    uint32_t DbA = (uint32_t)__cvta_generic_to_shared(Db);
    uint32_t XTA = (uint32_t)__cvta_generic_to_shared(XT);
    uint32_t WsA = (uint32_t)__cvta_generic_to_shared(Ws);
    int tid = threadIdx.x, lane = tid&31, wid = tid>>5;
    int wm = wid>>3, wn = wid&7;       // 2 x 8 warps, 32x16 tiles (m1/m2/m4)
    int wm2 = wid>>2, wn2 = wid&3;     // 4 x 4 warps, 32x32 tiles (m3/m5)
    int g = lane>>2, tg = lane&3;
    int chunk = blockIdx.x;
    int bh = chunk >> 6, t0 = (chunk & 63) << 6;

    const float* kg = d_keys + ((size_t)bh*Lq + t0)*DHq;
    const float* vg = d_vals + ((size_t)bh*Lq + t0)*DHq;
#pragma unroll
    for (int u=tid; u<2048; u+=512){
        int r = u>>5, c = (u&31)*4;
        cpa16(KsA + (r*PT+c)*4, kg + u*4);
        cpa16(DbA + (r*PT+c)*4, vg + u*4);
    }
#pragma unroll
    for (int u=tid; u<4096; u+=512){
        int r = u>>5, c = (u&31)*4;
        cpa16(WsA + (r*PT+c)*4, d_w0T + u*4);
    }
    cpcommit();
    if (tid < 64) Lr[tid] = d_lr[(size_t)bh*Lq + t0 + tid];
    cpwait<0>();
    __syncthreads();

    // m1: h = K @ w0 ; h in regs; a = silu(h) -> Ab
    float hreg[2][2][4] = {};
    wtileLL<2,2,16>(ldsmBase(KsA, wm*32, PT, lane), PT,
                    ldsmBase(WsA, wn*16, PT, lane), PT, hreg);
#pragma unroll
    for (int mt=0;mt<2;mt++)
#pragma unroll
    for (int nt=0;nt<2;nt++)
#pragma unroll
    for (int e=0;e<4;e++){
        int row = wm*32 + mt*16 + g + ((e&2)?8:0);
        int col = wn*16 + nt*8 + 2*tg + (e&1);
        float h = hreg[mt][nt][e];
        Ab[row*PT+col] = f2tf32(h/(1.f+expf(-h)));
    }
    __syncthreads();
#pragma unroll
    for (int u=tid; u<4096; u+=512){
        int r = u>>5, c = (u&31)*4;
        cpa16(WsA + (r*PT+c)*4, d_w1T + u*4);
    }
    cpcommit(); cpwait<0>();
    __syncthreads();

    {   // m2: pred = a @ w1 ; dpred -> Db (row-major) AND XT (transposed)
        float acc[2][2][4] = {};
        wtileLL<2,2,16>(ldsmBase(AbA, wm*32, PT, lane), PT,
                        ldsmBase(WsA, wn*16, PT, lane), PT, acc);
#pragma unroll
        for (int mt=0;mt<2;mt++)
#pragma unroll
        for (int nt=0;nt<2;nt++)
#pragma unroll
        for (int e=0;e<4;e++){
            int row = wm*32 + mt*16 + g + ((e&2)?8:0);
            int col = wn*16 + nt*8 + 2*tg + (e&1);
            float v = __uint_as_float(Db[row*PT+col]);
            uint32_t dp = f2tf32(Lr[row]*(2.f/DHq)*(acc[mt][nt][e] - v));
            Db[row*PT+col]  = dp;
            XT[col*PXT+row] = dp;
        }
    }
    __syncthreads();

    {   // m3: g1^T = dpred^T @ a -> gmem (A from XT via ldsm, B = Ab scalar k-major)
        float acc[2][4][4] = {};
        wtileLS<2,4,8>(ldsmBase(XTA, wm2*32, PXT, lane), PXT, Ab, PT, acc, wn2*32, lane);
        float* G = d_g1 + (size_t)chunk*DHq*DHq;
#pragma unroll
        for (int mt=0;mt<2;mt++)
#pragma unroll
        for (int nt=0;nt<4;nt++){
            int row = wm2*32 + mt*16 + g;
            int col = wn2*32 + nt*8 + 2*tg;
            *(float2*)&G[row*DHq + col]     = make_float2(acc[mt][nt][0], acc[mt][nt][1]);
            *(float2*)&G[(row+8)*DHq + col] = make_float2(acc[mt][nt][2], acc[mt][nt][3]);
        }
    }

    {   // m4: da = dpred @ w1^T (B k-major scalar from Ws) ; dh = da*dsilu(h) -> XT
        float acc[2][2][4] = {};
        wtileLS<2,2,16>(ldsmBase(DbA, wm*32, PT, lane), PT, Ws, PT, acc, wn*16, lane);
        __syncthreads();    // all m3 XT reads done before overwrite
#pragma unroll
        for (int mt=0;mt<2;mt++)
#pragma unroll
        for (int nt=0;nt<2;nt++)
#pragma unroll
        for (int e=0;e<4;e++){
            int row = wm*32 + mt*16 + g + ((e&2)?8:0);
            int col = wn*16 + nt*8 + 2*tg + (e&1);
            float h = hreg[mt][nt][e];
            float s = 1.f/(1.f+expf(-h));
            XT[col*PXT+row] = f2tf32(acc[mt][nt][e] * s * (1.f + h*(1.f - s)));
        }
    }
    __syncthreads();

    {   // m5: g0^T = dh^T @ K -> gmem (A from XT via ldsm, B = Ks scalar k-major)
        float acc[2][4][4] = {};
        wtileLS<2,4,8>(ldsmBase(XTA, wm2*32, PXT, lane), PXT, Ks, PT, acc, wn2*32, lane);
        float* G = d_g0 + (size_t)chunk*DHq*DHq;
#pragma unroll
        for (int mt=0;mt<2;mt++)
#pragma unroll
        for (int nt=0;nt<4;nt++){
            int row = wm2*32 + mt*16 + g;
            int col = wn2*32 + nt*8 + 2*tg;
            *(float2*)&G[row*DHq + col]     = make_float2(acc[mt][nt][0], acc[mt][nt][1]);
            *(float2*)&G[(row+8)*DHq + col] = make_float2(acc[mt][nt][2], acc[mt][nt][3]);
        }
    }
}

// ---------------- scan (transposed layout; float4-vectorized; writes tf32-rounded) ----------------
__global__ void __launch_bounds__(128) scan_kernel()
{
    __shared__ float ams[Nq], dcs[Nq];
    int gid = blockIdx.x*128 + threadIdx.x;     // BH * 4096 threads, 4 elems each
    int bh = gid >> 12;
    int e  = (gid & 4095) * 4;
    if (threadIdx.x < Nq){
        ams[threadIdx.x] = d_am[(size_t)bh*Nq + threadIdx.x];
        dcs[threadIdx.x] = d_dc[(size_t)bh*Nq + threadIdx.x];
    }
    __syncthreads();
    float m0[4]={0,0,0,0}, u0[4]={0,0,0,0}, m1[4]={0,0,0,0}, u1[4]={0,0,0,0};
    float4 wa = *(const float4*)&d_w0T[e];
    float4 wb = *(const float4*)&d_w1T[e];
    float wav[4] = {wa.x,wa.y,wa.z,wa.w};
    float wbv[4] = {wb.x,wb.y,wb.z,wb.w};
    size_t base = ((size_t)bh*Nq)*16384 + e;
    for (int n=0;n<Nq;n++){
        float a = ams[n], d = 1.f - dcs[n];
        size_t off = base + (size_t)n*16384;
        float4 g0v = *(const float4*)&d_g0[off];
        float4 g1v = *(const float4*)&d_g1[off];
        float g0a[4] = {g0v.x,g0v.y,g0v.z,g0v.w};
        float g1a[4] = {g1v.x,g1v.y,g1v.z,g1v.w};
        float o0[4], o1[4];
#pragma unroll
        for (int i=0;i<4;i++){
            m0[i] = a*m0[i] - g0a[i];  u0[i] = d*u0[i] + m0[i];  o0[i] = f2tf32f(wav[i] + u0[i]);
            m1[i] = a*m1[i] - g1a[i];  u1[i] = d*u1[i] + m1[i];  o1[i] = f2tf32f(wbv[i] + u1[i]);
        }
        *(float4*)&d_w0t[off] = make_float4(o0[0],o0[1],o0[2],o0[3]);
        *(float4*)&d_w1t[off] = make_float4(o1[0],o1[1],o1[2],o1[3]);
    }
}

// ---------------- retrieve MLP + RMSNorm + gate (in-place tile, 2 CTA/SM) ----------------
__global__ void __launch_bounds__(256,2) retrieve_kernel(const float* __restrict__ gamma)
{
    extern __shared__ uint32_t smr[];
    uint32_t* QA = smr;            // 64*PT: q -> a -> o (in place)
    uint32_t* Ws = QA + 64*PT;     // 128*PT: w0t, then w1t
    uint32_t QAA = (uint32_t)__cvta_generic_to_shared(QA);
    uint32_t WsA = (uint32_t)__cvta_generic_to_shared(Ws);
    int tid = threadIdx.x, lane = tid&31, wid = tid>>5;
    int wm = wid>>2, wn = wid&3;
    int g = lane>>2, tg = lane&3;
    int chunk = blockIdx.x;
    int bh = chunk >> 6, n = chunk & 63;
    int b = bh >> 2, h = bh & 3;

    const float* qg  = d_quer + ((size_t)bh*Lq + n*Cq)*DHq;
    const float* w0c = d_w0t + (size_t)chunk*DHq*DHq;
    const float* w1c = d_w1t + (size_t)chunk*DHq*DHq;
#pragma unroll
    for (int u=tid; u<2048; u+=256){
        int r = u>>5, c = (u&31)*4;
        cpa16(QAA + (r*PT+c)*4, qg + u*4);
    }
#pragma unroll
    for (int u=tid; u<4096; u+=256){
        int r = u>>5, c = (u&31)*4;
        cpa16(WsA + (r*PT+c)*4, w0c + u*4);
    }
    cpcommit(); cpwait<0>();
    __syncthreads();

    // m1: a = silu(q @ w0_t)  — compute to regs, sync, write in place
    float acc1[2][4][4] = {};
    wtileLL<2,4,16>(ldsmBase(QAA, wm*32, PT, lane), PT,
                    ldsmBase(WsA, wn*32, PT, lane), PT, acc1);
    __syncthreads();           // everyone done reading q and w0t
#pragma unroll
    for (int u=tid; u<4096; u+=256){     // start w1t load into freed Ws
        int r = u>>5, c = (u&31)*4;
        cpa16(WsA + (r*PT+c)*4, w1c + u*4);
    }
    cpcommit();
#pragma unroll
    for (int mt=0;mt<2;mt++)
#pragma unroll
    for (int nt=0;nt<4;nt++)
#pragma unroll
    for (int e=0;e<4;e++){
        int row = wm*32 + mt*16 + g + ((e&2)?8:0);
        int col = wn*32 + nt*8 + 2*tg + (e&1);
        float hh = acc1[mt][nt][e];
        QA[row*PT+col] = f2tf32(hh/(1.f+expf(-hh)));
    }
    cpwait<0>();
    __syncthreads();

    // m2: o = a @ w1_t — compute to regs, sync, write in place (fp32 bits)
    float acc2[2][4][4] = {};
    wtileLL<2,4,16>(ldsmBase(QAA, wm*32, PT, lane), PT,
                    ldsmBase(WsA, wn*32, PT, lane), PT, acc2);
    __syncthreads();
#pragma unroll
    for (int mt=0;mt<2;mt++)
#pragma unroll
    for (int nt=0;nt<4;nt++)
#pragma unroll
    for (int e=0;e<4;e++){
        int row = wm*32 + mt*16 + g + ((e&2)?8:0);
        int col = wn*32 + nt*8 + 2*tg + (e&1);
        QA[row*PT+col] = __float_as_uint(acc2[mt][nt][e]);
    }
    __syncthreads();

    const float* Of = (const float*)QA;
    int w = tid >> 5;
#pragma unroll
    for (int rr=0; rr<8; rr++){
        int row = w*8 + rr;
        float v0 = Of[row*PT + lane];
        float v1 = Of[row*PT + lane + 32];
        float v2 = Of[row*PT + lane + 64];
        float v3 = Of[row*PT + lane + 96];
        float ss = v0*v0 + v1*v1 + v2*v2 + v3*v3;
#pragma unroll
        for (int off=16;off;off>>=1) ss += __shfl_xor_sync(0xffffffffu, ss, off);
        float sc = rsqrtf(ss*(1.f/DHq) + EPSq);
        int t = n*Cq + row;
        float gt = d_gatev[((size_t)b*Lq + t)*Hq + h];
        float* dst = d_comb + ((size_t)b*Lq + t)*DIMq + h*DHq;
        dst[lane     ] = f2tf32f(v0*sc*(gamma[h*DHq + lane     ] + 1.f)*gt);
        dst[lane + 32] = f2tf32f(v1*sc*(gamma[h*DHq + lane + 32] + 1.f)*gt);
        dst[lane + 64] = f2tf32f(v2*sc*(gamma[h*DHq + lane + 64] + 1.f)*gt);
        dst[lane + 96] = f2tf32f(v3*sc*(gamma[h*DHq + lane + 96] + 1.f)*gt);
    }
}

// ---------------- empty-embed fill ----------------
__global__ void empty_fill_kernel(const float* __restrict__ emb, float* __restrict__ out)
{
    int gid = blockIdx.x*blockDim.x + threadIdx.x;
    int total = Bq*(Cq-1)*DIMq;
    if (gid >= total) return;
    int d = gid & (DIMq-1);
    int row = gid / DIMq;
    int b = row / (Cq-1), t = row % (Cq-1);
    out[((size_t)b*Lq + t)*DIMq + d] = emb[d];
}

// ---------------- launch ----------------
extern "C" void kernel_launch(void* const* d_in, const int* in_sizes, int n_in,
                              void* d_out, int out_size)
{
    const float* seq      = (const float*)d_in[0];
    const float* ss       = (const float*)d_in[1];
    const float* rs       = (const float*)d_in[2];
    const float* w_q      = (const float*)d_in[3];
    const float* w_kv     = (const float*)d_in[4];
    const float* w_ada    = (const float*)d_in[5];
    const float* w_mom    = (const float*)d_in[6];
    const float* w_dec    = (const float*)d_in[7];
    const float* w0       = (const float*)d_in[8];
    const float* w1       = (const float*)d_in[9];
    const float* gamma    = (const float*)d_in[10];
    const float* w_gate   = (const float*)d_in[11];
    const float* w_comb   = (const float*)d_in[12];
    const float* emb      = (const float*)d_in[13];
    float* out = (float*)d_out;

    float *p_snorm, *p_rnorm, *p_keys, *p_vals, *p_quer, *p_comb;
    float *p_wkvT, *p_wqT, *p_wcT;
    cudaGetSymbolAddress((void**)&p_snorm, d_s_norm);
    cudaGetSymbolAddress((void**)&p_rnorm, d_r_norm);
    cudaGetSymbolAddress((void**)&p_keys,  d_keys);
    cudaGetSymbolAddress((void**)&p_vals,  d_vals);
    cudaGetSymbolAddress((void**)&p_quer,  d_quer);
    cudaGetSymbolAddress((void**)&p_comb,  d_comb);
    cudaGetSymbolAddress((void**)&p_wkvT,  d_wkvT);
    cudaGetSymbolAddress((void**)&p_wqT,   d_wqT);
    cudaGetSymbolAddress((void**)&p_wcT,   d_wcT);

    const int SMEM_GEMM = 3*GSTG*4;                               // 110592 B
    const int SMEM_G = (3*64*PT + 128*PXT + 128*PT)*4 + 256;      // ~204 KB
    const int SMEM_R = (64*PT + 128*PT)*4;                        // 101376 B
    cudaFuncSetAttribute(gemm_tc<0>, cudaFuncAttributeMaxDynamicSharedMemorySize, SMEM_GEMM);
    cudaFuncSetAttribute(gemm_tc<1>, cudaFuncAttributeMaxDynamicSharedMemorySize, SMEM_GEMM);
    cudaFuncSetAttribute(gemm_tc<2>, cudaFuncAttributeMaxDynamicSharedMemorySize, SMEM_GEMM);
    cudaFuncSetAttribute(chunk_grad_kernel, cudaFuncAttributeMaxDynamicSharedMemorySize, SMEM_G);
    cudaFuncSetAttribute(retrieve_kernel,   cudaFuncAttributeMaxDynamicSharedMemorySize, SMEM_R);

    // fork/join streams (capture-safe; 2 streams proven allocation-clean)
    cudaStream_t s1, s2;
    cudaStreamCreateWithFlags(&s1, cudaStreamNonBlocking);
    cudaStreamCreateWithFlags(&s2, cudaStreamNonBlocking);
    cudaEvent_t e0, et, en, eq, em;
    cudaEventCreateWithFlags(&e0, cudaEventDisableTiming);
    cudaEventCreateWithFlags(&et, cudaEventDisableTiming);
    cudaEventCreateWithFlags(&en, cudaEventDisableTiming);
    cudaEventCreateWithFlags(&eq, cudaEventDisableTiming);
    cudaEventCreateWithFlags(&em, cudaEventDisableTiming);

    cudaEventRecord(e0, 0);
    cudaStreamWaitEvent(s1, e0, 0);
    cudaStreamWaitEvent(s2, e0, 0);

    // s1: merged transposes + empty fill
    transpose_all<<<dim3(32,16,5), dim3(32,8), 0, s1>>>(w_kv, w_q, w_comb, w0, w1);
    empty_fill_kernel<<<(Bq*(Cq-1)*DIMq + 255)/256, 256, 0, s1>>>(emb, out);
    cudaEventRecord(et, s1);

    // main: rmsnorms + fused projections
    norm_kernel<<<Bq*Lq, 128>>>(seq, ss, rs, w_ada, w_gate);
    cudaEventRecord(en, 0);

    // s1: fused chunk-mean + momdec
    cudaStreamWaitEvent(s1, en, 0);
    cmeanmom_kernel<<<Bq*Nq, 512, 0, s1>>>(w_mom, w_dec);
    cudaEventRecord(em, s1);

    // s2: query projection (concurrent with kv projection)
    cudaStreamWaitEvent(s2, en, 0);
    cudaStreamWaitEvent(s2, et, 0);
    gemm_tc<1><<<dim3((Hq*DHq)/128, (Bq*Lq)/128), 256, SMEM_GEMM, s2>>>(p_rnorm, p_wqT, p_quer, nullptr, DIMq);
    cudaEventRecord(eq, s2);

    // main chain (monolithic kernels — proven fastest structure)
    cudaStreamWaitEvent(0, et, 0);
    gemm_tc<0><<<dim3((2*Hq*DHq)/128, (Bq*Lq)/128), 256, SMEM_GEMM>>>(p_snorm, p_wkvT, p_keys, p_vals, DIMq);
    chunk_grad_kernel<<<NCHUNK, 512, SMEM_G>>>();
    cudaStreamWaitEvent(0, em, 0);
    scan_kernel<<<(BHq*4096)/128, 128>>>();
    cudaStreamWaitEvent(0, eq, 0);
    retrieve_kernel<<<NCHUNK, 256, SMEM_R>>>(gamma);
    gemm_tc<2><<<dim3(DIMq/128, (Bq*Lq)/128), 256, SMEM_GEMM>>>(p_comb, p_wcT, out, nullptr, Hq*DHq);

    cudaStreamCaptureStatus cap = cudaStreamCaptureStatusNone;
    cudaStreamIsCapturing(0, &cap);
    if (cap == cudaStreamCaptureStatusNone){
        cudaStreamDestroy(s1); cudaStreamDestroy(s2);
        cudaEventDestroy(e0); cudaEventDestroy(et); cudaEventDestroy(en);
        cudaEventDestroy(eq); cudaEventDestroy(em);
    }
}

// round 17
// speedup vs baseline: 1.0590x; 1.0590x over previous
#include <cuda_runtime.h>
#include <cuda_bf16.h>
#include <math.h>
#include <stdint.h>

// ---------------- problem constants ----------------
#define Bq   2
#define Lq   4096
#define DIMq 512
#define Hq   4
#define DHq  128
#define Cq   64
#define Nq   64          // L / C
#define BHq  8           // B * H
#define NCHUNK 512       // BH * N
#define MAXLR 0.01f
#define EPSq  1e-6f

// ---------------- scratch (device globals; allocation-free) ----------------
// buffers marked (tf32) hold fp32 values pre-rounded to tf32.
__device__ float d_s_norm[Bq*Lq*DIMq];       // (tf32)
__device__ float d_r_norm[Bq*Lq*DIMq];       // (tf32)
__device__ float d_keys  [BHq*Lq*DHq];       // (tf32)
__device__ float d_vals  [BHq*Lq*DHq];       // fp32
__device__ float d_quer  [BHq*Lq*DHq];       // (tf32)
__device__ float d_lr    [BHq*Lq];
__device__ float d_am    [BHq*Nq];
__device__ float d_dc    [BHq*Nq];
__device__ float d_g0    [NCHUNK*DHq*DHq];   // fp32, TRANSPOSED layout
__device__ float d_g1    [NCHUNK*DHq*DHq];   // fp32, TRANSPOSED layout
__device__ float d_w0t   [NCHUNK*DHq*DHq];   // (tf32), TRANSPOSED layout
__device__ float d_w1t   [NCHUNK*DHq*DHq];   // (tf32), TRANSPOSED layout
__device__ float d_comb  [Bq*Lq*DIMq];       // (tf32)
__device__ float d_gatev [Bq*Lq*Hq];
// pretransposed weights, (tf32)
__device__ float d_wkvT[2*Hq*DHq*DIMq];
__device__ float d_wqT [Hq*DHq*DIMq];
__device__ float d_wcT [DIMq*Hq*DHq];
__device__ float d_w0T [DHq*DHq];
__device__ float d_w1T [DHq*DHq];

__device__ __forceinline__ float sigm(float x){ return 1.f/(1.f+expf(-x)); }

// ---------------- tf32 mma primitives ----------------
__device__ __forceinline__ uint32_t f2tf32(float x){
    uint32_t r; asm("cvt.rna.tf32.f32 %0, %1;" : "=r"(r) : "f"(x)); return r;
}
__device__ __forceinline__ float f2tf32f(float x){ return __uint_as_float(f2tf32(x)); }

__device__ __forceinline__ void mma8(float (&c)[4],
                                     uint32_t a0,uint32_t a1,uint32_t a2,uint32_t a3,
                                     uint32_t b0,uint32_t b1){
    asm volatile("mma.sync.aligned.m16n8k8.row.col.f32.tf32.tf32.f32 "
        "{%0,%1,%2,%3},{%4,%5,%6,%7},{%8,%9},{%0,%1,%2,%3};"
        : "+f"(c[0]),"+f"(c[1]),"+f"(c[2]),"+f"(c[3])
        : "r"(a0),"r"(a1),"r"(a2),"r"(a3),"r"(b0),"r"(b1));
}

__device__ __forceinline__ void ldsm4(uint32_t* r, uint32_t addr){
    asm volatile("ldmatrix.sync.aligned.m8n8.x4.shared.b16 {%0,%1,%2,%3}, [%4];"
        : "=r"(r[0]),"=r"(r[1]),"=r"(r[2]),"=r"(r[3]) : "r"(addr));
}

__device__ __forceinline__ uint32_t ldsmBase(uint32_t shAddr, int rbase, int ap, int lane){
    return shAddr + (uint32_t)(((rbase + (lane&15))*ap + ((lane>>4)<<2))*4);
}

// ---------------- cp.async helpers (.cg — bypass L1, data consumed once) ----------------
__device__ __forceinline__ void cpa16(uint32_t dst, const float* src){
    asm volatile("cp.async.cg.shared.global [%0],[%1],16;"::"r"(dst),"l"(src));
}
__device__ __forceinline__ void cpa16z(uint32_t dst, const float* src, bool p){
    int sz = p ? 16 : 0;
    asm volatile("cp.async.cg.shared.global [%0],[%1],16,%2;"::"r"(dst),"l"(src),"r"(sz));
}
__device__ __forceinline__ void cpcommit(){ asm volatile("cp.async.commit_group;"); }
template<int N> __device__ __forceinline__ void cpwait(){ asm volatile("cp.async.wait_group %0;"::"n"(N)); }

// both-side ldmatrix warp tile
template<int MT,int NT,int KS>
__device__ __forceinline__ void wtileLL(uint32_t aB,int ap,uint32_t bB,int bp,
                                        float (&acc)[MT][NT][4])
{
#pragma unroll
    for (int ks=0;ks<KS;ks++){
        int k0 = ks*8;
        uint32_t af[MT][4];
#pragma unroll
        for (int mt=0;mt<MT;mt++)
            ldsm4(af[mt], aB + (uint32_t)((mt*16*ap + k0)*4));
        uint32_t bq[NT/2][4];
#pragma unroll
        for (int nt2=0;nt2<NT/2;nt2++)
            ldsm4(bq[nt2], bB + (uint32_t)((nt2*16*bp + k0)*4));
#pragma unroll
        for (int mt=0;mt<MT;mt++)
#pragma unroll
            for (int nt=0;nt<NT;nt++)
                mma8(acc[mt][nt], af[mt][0],af[mt][1],af[mt][2],af[mt][3],
                     bq[nt>>1][nt&1], bq[nt>>1][2+(nt&1)]);
    }
}

// A ldmatrix, B scalar (k-major)
template<int MT,int NT,int KS>
__device__ __forceinline__ void wtileLS(uint32_t aB,int ap,const uint32_t* B,int bp,
                                        float (&acc)[MT][NT][4], int cbase, int lane)
{
    int g = lane>>2, tg = lane&3;
#pragma unroll
    for (int ks=0;ks<KS;ks++){
        int k0 = ks*8;
        uint32_t af[MT][4];
#pragma unroll
        for (int mt=0;mt<MT;mt++)
            ldsm4(af[mt], aB + (uint32_t)((mt*16*ap + k0)*4));
        uint32_t bf[NT][2];
#pragma unroll
        for (int nt=0;nt<NT;nt++){
            int n = cbase + nt*8 + g;
            bf[nt][0] = B[(k0+tg)*bp + n];
            bf[nt][1] = B[(k0+tg+4)*bp + n];
        }
#pragma unroll
        for (int mt=0;mt<MT;mt++)
#pragma unroll
            for (int nt=0;nt<NT;nt++)
                mma8(acc[mt][nt], af[mt][0],af[mt][1],af[mt][2],af[mt][3],
                     bf[nt][0],bf[nt][1]);
    }
}

// ---------------- merged transpose kernel (all 5 weights, tf32-rounded) ----------------
__global__ void __launch_bounds__(256) transpose_all(const float* __restrict__ w_kv,
                                                     const float* __restrict__ w_q,
                                                     const float* __restrict__ w_comb,
                                                     const float* __restrict__ w0,
                                                     const float* __restrict__ w1)
{
    __shared__ float t[32][33];
    int z = blockIdx.z;
    const float* in; float* out; int R, Cc;
    switch (z){
        case 0: in = w_kv;   out = d_wkvT; R = DIMq;   Cc = 2*Hq*DHq; break;
        case 1: in = w_q;    out = d_wqT;  R = DIMq;   Cc = Hq*DHq;   break;
        case 2: in = w_comb; out = d_wcT;  R = Hq*DHq; Cc = DIMq;     break;
        case 3: in = w0;     out = d_w0T;  R = DHq;    Cc = DHq;      break;
        default:in = w1;     out = d_w1T;  R = DHq;    Cc = DHq;      break;
    }
    int bx = blockIdx.x*32, by = blockIdx.y*32;
    if (bx >= Cc || by >= R) return;
#pragma unroll
    for (int i=0;i<4;i++)
        t[threadIdx.y + 8*i][threadIdx.x] = in[(size_t)(by + threadIdx.y + 8*i)*Cc + bx + threadIdx.x];
    __syncthreads();
#pragma unroll
    for (int i=0;i<4;i++)
        out[(size_t)(bx + threadIdx.y + 8*i)*R + by + threadIdx.x] = f2tf32f(t[threadIdx.x][threadIdx.y + 8*i]);
}

// ---------------- K1: per-token rmsnorm + fused lr/gate projections ----------------
__global__ void __launch_bounds__(128) norm_kernel(const float* __restrict__ seq,
                                                   const float* __restrict__ ss,
                                                   const float* __restrict__ rs,
                                                   const float* __restrict__ w_ada,
                                                   const float* __restrict__ w_gate)
{
    int token = blockIdx.x;              // b*L + t
    int tid = threadIdx.x;
    int lane = tid & 31, w = tid >> 5;
    const float* x = seq + (size_t)token*DIMq;
    float v[4]; float acc = 0.f;
#pragma unroll
    for (int i=0;i<4;i++){ v[i] = x[tid + 128*i]; acc += v[i]*v[i]; }
#pragma unroll
    for (int off=16;off;off>>=1) acc += __shfl_xor_sync(0xffffffffu, acc, off);
    __shared__ float red[4];
    __shared__ float red8[4][8];
    if (lane==0) red[w] = acc;
    __syncthreads();
    float tot = red[0]+red[1]+red[2]+red[3];
    float rms = rsqrtf(tot*(1.f/DIMq) + EPSq);
    float p[8] = {0,0,0,0,0,0,0,0};
#pragma unroll
    for (int i=0;i<4;i++){
        int d = tid + 128*i;
        float y = v[i]*rms;
        float ysv = y*ss[d], yrv = y*rs[d];
        d_s_norm[(size_t)token*DIMq + d] = f2tf32f(ysv);
        d_r_norm[(size_t)token*DIMq + d] = f2tf32f(yrv);
#pragma unroll
        for (int h=0;h<4;h++){
            p[h]   += ysv*w_ada [d*4+h];
            p[4+h] += yrv*w_gate[d*4+h];
        }
    }
#pragma unroll
    for (int h=0;h<8;h++)
#pragma unroll
        for (int off=16;off;off>>=1) p[h] += __shfl_xor_sync(0xffffffffu, p[h], off);
    if (lane==0)
#pragma unroll
        for (int h=0;h<8;h++) red8[w][h] = p[h];
    __syncthreads();
    if (tid < 8){
        float s = red8[0][tid]+red8[1][tid]+red8[2][tid]+red8[3][tid];
        int b = token >> 12, t = token & (Lq-1);
        if (tid < 4)
            d_lr[((size_t)(b*Hq+tid))*Lq + t] = sigm(s)*MAXLR;
        else if (t >= Cq-1)
            d_gatev[((size_t)b*Lq + (t-(Cq-1)))*Hq + (tid-4)] = sigm(s);
    }
}

// ---------------- fused chunk-mean + ada_mom/decay ----------------
__global__ void __launch_bounds__(512) cmeanmom_kernel(const float* __restrict__ wm,
                                                       const float* __restrict__ wd)
{
    __shared__ float redw[16][8];
    int bn = blockIdx.x;            // b*N + n
    int d = threadIdx.x;
    int lane = d & 31, w = d >> 5;
    int b = bn / Nq, n = bn % Nq;
    const float* base = d_s_norm + ((size_t)b*Lq + n*Cq)*DIMq + d;
    float acc = 0.f;
#pragma unroll 8
    for (int c=0;c<Cq;c++) acc += base[(size_t)c*DIMq];
    float mean = acc*(1.f/Cq);
    float p[8];
#pragma unroll
    for (int h=0;h<4;h++){
        p[h]   = mean*wm[d*4+h];
        p[4+h] = mean*wd[d*4+h];
    }
#pragma unroll
    for (int h=0;h<8;h++)
#pragma unroll
        for (int off=16;off;off>>=1) p[h] += __shfl_xor_sync(0xffffffffu, p[h], off);
    if (lane==0)
#pragma unroll
        for (int h=0;h<8;h++) redw[w][h] = p[h];
    __syncthreads();
    if (d < 8){
        float s = 0.f;
#pragma unroll
        for (int i=0;i<16;i++) s += redw[i][d];
        if (d < 4) d_am[(size_t)(b*Hq+d)*Nq + n]     = sigm(s);
        else       d_dc[(size_t)(b*Hq+d-4)*Nq + n]  = sigm(s);
    }
}

// ---------------- big GEMM, tf32 TC, 128x128 tiles, cp.async 3-stage ----------------
// MODE 0: keys/vals head-major; MODE 1: A shifted from r_norm, out queries; MODE 2: out shifted
#define GAP 36
#define GBP 36
#define GSTG (128*GAP + 128*GBP)
template<int MODE>
__global__ void __launch_bounds__(256,2) gemm_tc(const float* __restrict__ A,
                                                 const float* __restrict__ WT,
                                                 float* __restrict__ out0,
                                                 float* __restrict__ out1,
                                                 int K)
{
    extern __shared__ uint32_t sh[];
    uint32_t shAddr = (uint32_t)__cvta_generic_to_shared(sh);
    int tid = threadIdx.x, lane = tid & 31, wid = tid >> 5;
    int wm = wid >> 1, wn = wid & 1;       // 4 x 2 warps, 32x64 tiles
    int m0 = blockIdx.y*128, n0 = blockIdx.x*128;
    float acc[2][8][4] = {};
    int ar = tid>>3, ac4 = tid&7;          // rows ar+32i, 16B col ac4

    const int NK = K/32;
    auto issue = [&](int kt){
        int k0 = kt*32;
        uint32_t aB = shAddr + (uint32_t)((kt%3)*GSTG*4);
        uint32_t bB = aB + 128*GAP*4;
#pragma unroll
        for (int i=0;i<4;i++){
            int gr = m0 + ar + 32*i;
            uint32_t d = aB + (uint32_t)(((ar+32*i)*GAP + ac4*4)*4);
            if (MODE==1){
                int t = gr & (Lq-1);
                cpa16z(d, &A[(size_t)(gr+Cq-1)*K + k0 + ac4*4], t <= Lq-Cq);
            } else {
                cpa16(d, &A[(size_t)gr*K + k0 + ac4*4]);
            }
        }
#pragma unroll
        for (int i=0;i<4;i++)
            cpa16(bB + (uint32_t)(((ar+32*i)*GBP + ac4*4)*4),
                  &WT[(size_t)(n0 + ar + 32*i)*K + k0 + ac4*4]);
        cpcommit();
    };

    issue(0);
    if (NK>1) issue(1);
#pragma unroll 1
    for (int kt=0; kt<NK; kt++){
        if (kt == NK-1) cpwait<0>(); else cpwait<1>();
        __syncthreads();
        if (kt+2 < NK) issue(kt+2);
        uint32_t aB = shAddr + (uint32_t)((kt%3)*GSTG*4);
        uint32_t bB = aB + 128*GAP*4;
        wtileLL<2,8,4>(ldsmBase(aB, wm*32, GAP, lane), GAP,
                       ldsmBase(bB, wn*64, GBP, lane), GBP, acc);
    }

    int g = lane>>2, tg = lane&3;
#pragma unroll
    for (int mt=0;mt<2;mt++)
#pragma unroll
    for (int nt=0;nt<8;nt++)
#pragma unroll
    for (int eh=0;eh<2;eh++){
        int row = m0 + wm*32 + mt*16 + g + eh*8;
        int col = n0 + wn*64 + nt*8 + 2*tg;
        float va = acc[mt][nt][eh*2+0];
        float vb = acc[mt][nt][eh*2+1];
        int b = row >> 12, t = row & (Lq-1);
        if (MODE==0){
            if (col < Hq*DHq){
                int h = col>>7, d = col&127;
                *(float2*)&out0[((size_t)(b*Hq+h)*Lq + t)*DHq + d] =
                    make_float2(f2tf32f(va), f2tf32f(vb));
            } else {
                int c2 = col - Hq*DHq; int h = c2>>7, d = c2&127;
                *(float2*)&out1[((size_t)(b*Hq+h)*Lq + t)*DHq + d] = make_float2(va, vb);
            }
        } else if (MODE==1){
            int h = col>>7, d = col&127;
            *(float2*)&out0[((size_t)(b*Hq+h)*Lq + t)*DHq + d] =
                make_float2(f2tf32f(va), f2tf32f(vb));
        } else {
            if (t <= Lq - Cq)
                *(float2*)&out0[((size_t)b*Lq + t + Cq - 1)*DIMq + col] = make_float2(va, vb);
        }
    }
}

// ---------------- per-chunk kernels ----------------
#define PT  132
#define PXT 68   // pitch of 128x64 transposed tiles

// ---------------- chunk gradient (256 threads — proven best) ----------------
__global__ void __launch_bounds__(256) chunk_grad_kernel()
{
    extern __shared__ uint32_t smu[];
    uint32_t* Ks = smu;            // 64*PT keys (tf32)
    uint32_t* Ab = Ks + 64*PT;     // a=silu(h) (tf32)
    uint32_t* Db = Ab + 64*PT;     // v (fp32), later dpred (tf32) row-major
    uint32_t* XT = Db + 64*PT;     // 128*PXT: dpred^T, later dh^T (tf32)
    uint32_t* Ws = XT + 128*PXT;   // 128*PT weights (w0T, then w1T)
    float* Lr = (float*)(Ws + 128*PT);
    uint32_t KsA = (uint32_t)__cvta_generic_to_shared(Ks);
    uint32_t AbA = (uint32_t)__cvta_generic_to_shared(Ab);
    uint32_t DbA = (uint32_t)__cvta_generic_to_shared(Db);
    uint32_t XTA = (uint32_t)__cvta_generic_to_shared(XT);
    uint32_t WsA = (uint32_t)__cvta_generic_to_shared(Ws);
    int tid = threadIdx.x, lane = tid&31, wid = tid>>5;
    int wm = wid>>2, wn = wid&3;   // 2 x 4 warps
    int g = lane>>2, tg = lane&3;
    int chunk = blockIdx.x;
    int bh = chunk >> 6, t0 = (chunk & 63) << 6;

    const float* kg = d_keys + ((size_t)bh*Lq + t0)*DHq;
    const float* vg = d_vals + ((size_t)bh*Lq + t0)*DHq;
#pragma unroll
    for (int u=tid; u<2048; u+=256){
        int r = u>>5, c = (u&31)*4;
        cpa16(KsA + (r*PT+c)*4, kg + u*4);
        cpa16(DbA + (r*PT+c)*4, vg + u*4);
    }
#pragma unroll
    for (int u=tid; u<4096; u+=256){
        int r = u>>5, c = (u&31)*4;
        cpa16(WsA + (r*PT+c)*4, d_w0T + u*4);
    }
    cpcommit();
    if (tid < 64) Lr[tid] = d_lr[(size_t)bh*Lq + t0 + tid];
    cpwait<0>();
    __syncthreads();

    // m1: h = K @ w0 ; h in regs; a = silu(h) -> Ab
    float hreg[2][4][4] = {};
    wtileLL<2,4,16>(ldsmBase(KsA, wm*32, PT, lane), PT,
                    ldsmBase(WsA, wn*32, PT, lane), PT, hreg);
#pragma unroll
    for (int mt=0;mt<2;mt++)
#pragma unroll
    for (int nt=0;nt<4;nt++)
#pragma unroll
    for (int e=0;e<4;e++){
        int row = wm*32 + mt*16 + g + ((e&2)?8:0);
        int col = wn*32 + nt*8 + 2*tg + (e&1);
        float h = hreg[mt][nt][e];
        Ab[row*PT+col] = f2tf32(h/(1.f+expf(-h)));
    }
    __syncthreads();
#pragma unroll
    for (int u=tid; u<4096; u+=256){
        int r = u>>5, c = (u&31)*4;
        cpa16(WsA + (r*PT+c)*4, d_w1T + u*4);
    }
    cpcommit(); cpwait<0>();
    __syncthreads();

    {   // m2: pred = a @ w1 ; dpred -> Db (row-major) AND XT (transposed)
        float acc[2][4][4] = {};
        wtileLL<2,4,16>(ldsmBase(AbA, wm*32, PT, lane), PT,
                        ldsmBase(WsA, wn*32, PT, lane), PT, acc);
#pragma unroll
        for (int mt=0;mt<2;mt++)
#pragma unroll
        for (int nt=0;nt<4;nt++)
#pragma unroll
        for (int e=0;e<4;e++){
            int row = wm*32 + mt*16 + g + ((e&2)?8:0);
            int col = wn*32 + nt*8 + 2*tg + (e&1);
            float v = __uint_as_float(Db[row*PT+col]);
            uint32_t dp = f2tf32(Lr[row]*(2.f/DHq)*(acc[mt][nt][e] - v));
            Db[row*PT+col]  = dp;
            XT[col*PXT+row] = dp;
        }
    }
    __syncthreads();

    {   // m3: g1^T = dpred^T @ a -> gmem (A from XT via ldsm, B = Ab scalar k-major)
        float acc[4][4][4] = {};
        wtileLS<4,4,8>(ldsmBase(XTA, wm*64, PXT, lane), PXT, Ab, PT, acc, wn*32, lane);
        float* G = d_g1 + (size_t)chunk*DHq*DHq;
#pragma unroll
        for (int mt=0;mt<4;mt++)
#pragma unroll
        for (int nt=0;nt<4;nt++){
            int row = wm*64 + mt*16 + g;
            int col = wn*32 + nt*8 + 2*tg;
            *(float2*)&G[row*DHq + col]     = make_float2(acc[mt][nt][0], acc[mt][nt][1]);
            *(float2*)&G[(row+8)*DHq + col] = make_float2(acc[mt][nt][2], acc[mt][nt][3]);
        }
    }

    {   // m4: da = dpred @ w1^T (B k-major scalar from Ws) ; dh = da*dsilu(h) -> XT
        float acc[2][4][4] = {};
        wtileLS<2,4,16>(ldsmBase(DbA, wm*32, PT, lane), PT, Ws, PT, acc, wn*32, lane);
        __syncthreads();    // all m3 XT reads done before overwrite
#pragma unroll
        for (int mt=0;mt<2;mt++)
#pragma unroll
        for (int nt=0;nt<4;nt++)
#pragma unroll
        for (int e=0;e<4;e++){
            int row = wm*32 + mt*16 + g + ((e&2)?8:0);
            int col = wn*32 + nt*8 + 2*tg + (e&1);
            float h = hreg[mt][nt][e];
            float s = 1.f/(1.f+expf(-h));
            XT[col*PXT+row] = f2tf32(acc[mt][nt][e] * s * (1.f + h*(1.f - s)));
        }
    }
    __syncthreads();

    {   // m5: g0^T = dh^T @ K -> gmem (A from XT via ldsm, B = Ks scalar k-major)
        float acc[4][4][4] = {};
        wtileLS<4,4,8>(ldsmBase(XTA, wm*64, PXT, lane), PXT, Ks, PT, acc, wn*32, lane);
        float* G = d_g0 + (size_t)chunk*DHq*DHq;
#pragma unroll
        for (int mt=0;mt<4;mt++)
#pragma unroll
        for (int nt=0;nt<4;nt++){
            int row = wm*64 + mt*16 + g;
            int col = wn*32 + nt*8 + 2*tg;
            *(float2*)&G[row*DHq + col]     = make_float2(acc[mt][nt][0], acc[mt][nt][1]);
            *(float2*)&G[(row+8)*DHq + col] = make_float2(acc[mt][nt][2], acc[mt][nt][3]);
        }
    }
}

// ---------------- scan (float4-vectorized; next-iter prefetch; tf32-rounded) ----------------
__global__ void __launch_bounds__(128) scan_kernel()
{
    __shared__ float ams[Nq], dcs[Nq];
    int gid = blockIdx.x*128 + threadIdx.x;     // BH * 4096 threads, 4 elems each
    int bh = gid >> 12;
    int e  = (gid & 4095) * 4;
    if (threadIdx.x < Nq){
        ams[threadIdx.x] = d_am[(size_t)bh*Nq + threadIdx.x];
        dcs[threadIdx.x] = d_dc[(size_t)bh*Nq + threadIdx.x];
    }
    __syncthreads();
    float m0[4]={0,0,0,0}, u0[4]={0,0,0,0}, m1[4]={0,0,0,0}, u1[4]={0,0,0,0};
    float4 wa = *(const float4*)&d_w0T[e];
    float4 wb = *(const float4*)&d_w1T[e];
    float wav[4] = {wa.x,wa.y,wa.z,wa.w};
    float wbv[4] = {wb.x,wb.y,wb.z,wb.w};
    size_t base = ((size_t)bh*Nq)*16384 + e;
    // prefetch iteration 0
    float4 g0v = *(const float4*)&d_g0[base];
    float4 g1v = *(const float4*)&d_g1[base];
    for (int n=0;n<Nq;n++){
        size_t off = base + (size_t)n*16384;
        // prefetch next iteration before consuming current
        float4 ng0, ng1;
        if (n+1 < Nq){
            ng0 = *(const float4*)&d_g0[off + 16384];
            ng1 = *(const float4*)&d_g1[off + 16384];
        }
        float a = ams[n], d = 1.f - dcs[n];
        float g0a[4] = {g0v.x,g0v.y,g0v.z,g0v.w};
        float g1a[4] = {g1v.x,g1v.y,g1v.z,g1v.w};
        float o0[4], o1[4];
#pragma unroll
        for (int i=0;i<4;i++){
            m0[i] = a*m0[i] - g0a[i];  u0[i] = d*u0[i] + m0[i];  o0[i] = f2tf32f(wav[i] + u0[i]);
            m1[i] = a*m1[i] - g1a[i];  u1[i] = d*u1[i] + m1[i];  o1[i] = f2tf32f(wbv[i] + u1[i]);
        }
        *(float4*)&d_w0t[off] = make_float4(o0[0],o0[1],o0[2],o0[3]);
        *(float4*)&d_w1t[off] = make_float4(o1[0],o1[1],o1[2],o1[3]);
        g0v = ng0; g1v = ng1;
    }
}

// ---------------- retrieve MLP + RMSNorm + gate (in-place tile, 2 CTA/SM) ----------------
__global__ void __launch_bounds__(256,2) retrieve_kernel(const float* __restrict__ gamma)
{
    extern __shared__ uint32_t smr[];
    uint32_t* QA = smr;            // 64*PT: q -> a -> o (in place)
    uint32_t* Ws = QA + 64*PT;     // 128*PT: w0t, then w1t
    uint32_t QAA = (uint32_t)__cvta_generic_to_shared(QA);
    uint32_t WsA = (uint32_t)__cvta_generic_to_shared(Ws);
    int tid = threadIdx.x, lane = tid&31, wid = tid>>5;
    int wm = wid>>2, wn = wid&3;
    int g = lane>>2, tg = lane&3;
    int chunk = blockIdx.x;
    int bh = chunk >> 6, n = chunk & 63;
    int b = bh >> 2, h = bh & 3;

    const float* qg  = d_quer + ((size_t)bh*Lq + n*Cq)*DHq;
    const float* w0c = d_w0t + (size_t)chunk*DHq*DHq;
    const float* w1c = d_w1t + (size_t)chunk*DHq*DHq;
#pragma unroll
    for (int u=tid; u<2048; u+=256){
        int r = u>>5, c = (u&31)*4;
        cpa16(QAA + (r*PT+c)*4, qg + u*4);
    }
#pragma unroll
    for (int u=tid; u<4096; u+=256){
        int r = u>>5, c = (u&31)*4;
        cpa16(WsA + (r*PT+c)*4, w0c + u*4);
    }
    cpcommit(); cpwait<0>();
    __syncthreads();

    // m1: a = silu(q @ w0_t)  — compute to regs, sync, write in place
    float acc1[2][4][4] = {};
    wtileLL<2,4,16>(ldsmBase(QAA, wm*32, PT, lane), PT,
                    ldsmBase(WsA, wn*32, PT, lane), PT, acc1);
    __syncthreads();           // everyone done reading q and w0t
#pragma unroll
    for (int u=tid; u<4096; u+=256){     // start w1t load into freed Ws
        int r = u>>5, c = (u&31)*4;
        cpa16(WsA + (r*PT+c)*4, w1c + u*4);
    }
    cpcommit();
#pragma unroll
    for (int mt=0;mt<2;mt++)
#pragma unroll
    for (int nt=0;nt<4;nt++)
#pragma unroll
    for (int e=0;e<4;e++){
        int row = wm*32 + mt*16 + g + ((e&2)?8:0);
        int col = wn*32 + nt*8 + 2*tg + (e&1);
        float hh = acc1[mt][nt][e];
        QA[row*PT+col] = f2tf32(hh/(1.f+expf(-hh)));
    }
    cpwait<0>();
    __syncthreads();

    // m2: o = a @ w1_t — compute to regs, sync, write in place (fp32 bits)
    float acc2[2][4][4] = {};
    wtileLL<2,4,16>(ldsmBase(QAA, wm*32, PT, lane), PT,
                    ldsmBase(WsA, wn*32, PT, lane), PT, acc2);
    __syncthreads();
#pragma unroll
    for (int mt=0;mt<2;mt++)
#pragma unroll
    for (int nt=0;nt<4;nt++)
#pragma unroll
    for (int e=0;e<4;e++){
        int row = wm*32 + mt*16 + g + ((e&2)?8:0);
        int col = wn*32 + nt*8 + 2*tg + (e&1);
        QA[row*PT+col] = __float_as_uint(acc2[mt][nt][e]);
    }
    __syncthreads();

    const float* Of = (const float*)QA;
    int w = tid >> 5;
#pragma unroll
    for (int rr=0; rr<8; rr++){
        int row = w*8 + rr;
        float v0 = Of[row*PT + lane];
        float v1 = Of[row*PT + lane + 32];
        float v2 = Of[row*PT + lane + 64];
        float v3 = Of[row*PT + lane + 96];
        float ss = v0*v0 + v1*v1 + v2*v2 + v3*v3;
#pragma unroll
        for (int off=16;off;off>>=1) ss += __shfl_xor_sync(0xffffffffu, ss, off);
        float sc = rsqrtf(ss*(1.f/DHq) + EPSq);
        int t = n*Cq + row;
        float gt = d_gatev[((size_t)b*Lq + t)*Hq + h];
        float* dst = d_comb + ((size_t)b*Lq + t)*DIMq + h*DHq;
        dst[lane     ] = f2tf32f(v0*sc*(gamma[h*DHq + lane     ] + 1.f)*gt);
        dst[lane + 32] = f2tf32f(v1*sc*(gamma[h*DHq + lane + 32] + 1.f)*gt);
        dst[lane + 64] = f2tf32f(v2*sc*(gamma[h*DHq + lane + 64] + 1.f)*gt);
        dst[lane + 96] = f2tf32f(v3*sc*(gamma[h*DHq + lane + 96] + 1.f)*gt);
    }
}

// ---------------- empty-embed fill ----------------
__global__ void empty_fill_kernel(const float* __restrict__ emb, float* __restrict__ out)
{
    int gid = blockIdx.x*blockDim.x + threadIdx.x;
    int total = Bq*(Cq-1)*DIMq;
    if (gid >= total) return;
    int d = gid & (DIMq-1);
    int row = gid / DIMq;
    int b = row / (Cq-1), t = row % (Cq-1);
    out[((size_t)b*Lq + t)*DIMq + d] = emb[d];
}

// ---------------- launch ----------------
extern "C" void kernel_launch(void* const* d_in, const int* in_sizes, int n_in,
                              void* d_out, int out_size)
{
    const float* seq      = (const float*)d_in[0];
    const float* ss       = (const float*)d_in[1];
    const float* rs       = (const float*)d_in[2];
    const float* w_q      = (const float*)d_in[3];
    const float* w_kv     = (const float*)d_in[4];
    const float* w_ada    = (const float*)d_in[5];
    const float* w_mom    = (const float*)d_in[6];
    const float* w_dec    = (const float*)d_in[7];
    const float* w0       = (const float*)d_in[8];
    const float* w1       = (const float*)d_in[9];
    const float* gamma    = (const float*)d_in[10];
    const float* w_gate   = (const float*)d_in[11];
    const float* w_comb   = (const float*)d_in[12];
    const float* emb      = (const float*)d_in[13];
    float* out = (float*)d_out;

    float *p_snorm, *p_rnorm, *p_keys, *p_vals, *p_quer, *p_comb;
    float *p_wkvT, *p_wqT, *p_wcT;
    cudaGetSymbolAddress((void**)&p_snorm, d_s_norm);
    cudaGetSymbolAddress((void**)&p_rnorm, d_r_norm);
    cudaGetSymbolAddress((void**)&p_keys,  d_keys);
    cudaGetSymbolAddress((void**)&p_vals,  d_vals);
    cudaGetSymbolAddress((void**)&p_quer,  d_quer);
    cudaGetSymbolAddress((void**)&p_comb,  d_comb);
    cudaGetSymbolAddress((void**)&p_wkvT,  d_wkvT);
    cudaGetSymbolAddress((void**)&p_wqT,   d_wqT);
    cudaGetSymbolAddress((void**)&p_wcT,   d_wcT);

    const int SMEM_GEMM = 3*GSTG*4;                               // 110592 B
    const int SMEM_G = (3*64*PT + 128*PXT + 128*PT)*4 + 256;      // ~204 KB
    const int SMEM_R = (64*PT + 128*PT)*4;                        // 101376 B
    cudaFuncSetAttribute(gemm_tc<0>, cudaFuncAttributeMaxDynamicSharedMemorySize, SMEM_GEMM);
    cudaFuncSetAttribute(gemm_tc<1>, cudaFuncAttributeMaxDynamicSharedMemorySize, SMEM_GEMM);
    cudaFuncSetAttribute(gemm_tc<2>, cudaFuncAttributeMaxDynamicSharedMemorySize, SMEM_GEMM);
    cudaFuncSetAttribute(chunk_grad_kernel, cudaFuncAttributeMaxDynamicSharedMemorySize, SMEM_G);
    cudaFuncSetAttribute(retrieve_kernel,   cudaFuncAttributeMaxDynamicSharedMemorySize, SMEM_R);

    // fork/join streams (capture-safe; 2 streams proven allocation-clean)
    cudaStream_t s1, s2;
    cudaStreamCreateWithFlags(&s1, cudaStreamNonBlocking);
    cudaStreamCreateWithFlags(&s2, cudaStreamNonBlocking);
    cudaEvent_t e0, et, en, eq, em;
    cudaEventCreateWithFlags(&e0, cudaEventDisableTiming);
    cudaEventCreateWithFlags(&et, cudaEventDisableTiming);
    cudaEventCreateWithFlags(&en, cudaEventDisableTiming);
    cudaEventCreateWithFlags(&eq, cudaEventDisableTiming);
    cudaEventCreateWithFlags(&em, cudaEventDisableTiming);

    cudaEventRecord(e0, 0);
    cudaStreamWaitEvent(s1, e0, 0);
    cudaStreamWaitEvent(s2, e0, 0);

    // s1: merged transposes + empty fill
    transpose_all<<<dim3(32,16,5), dim3(32,8), 0, s1>>>(w_kv, w_q, w_comb, w0, w1);
    empty_fill_kernel<<<(Bq*(Cq-1)*DIMq + 255)/256, 256, 0, s1>>>(emb, out);
    cudaEventRecord(et, s1);

    // main: rmsnorms + fused projections
    norm_kernel<<<Bq*Lq, 128>>>(seq, ss, rs, w_ada, w_gate);
    cudaEventRecord(en, 0);

    // s1: fused chunk-mean + momdec
    cudaStreamWaitEvent(s1, en, 0);
    cmeanmom_kernel<<<Bq*Nq, 512, 0, s1>>>(w_mom, w_dec);
    cudaEventRecord(em, s1);

    // s2: query projection (concurrent with kv projection)
    cudaStreamWaitEvent(s2, en, 0);
    cudaStreamWaitEvent(s2, et, 0);
    gemm_tc<1><<<dim3((Hq*DHq)/128, (Bq*Lq)/128), 256, SMEM_GEMM, s2>>>(p_rnorm, p_wqT, p_quer, nullptr, DIMq);
    cudaEventRecord(eq, s2);

    // main chain (monolithic kernels — proven fastest structure)
    cudaStreamWaitEvent(0, et, 0);
    gemm_tc<0><<<dim3((2*Hq*DHq)/128, (Bq*Lq)/128), 256, SMEM_GEMM>>>(p_snorm, p_wkvT, p_keys, p_vals, DIMq);
    chunk_grad_kernel<<<NCHUNK, 256, SMEM_G>>>();
    cudaStreamWaitEvent(0, em, 0);
    scan_kernel<<<(BHq*4096)/128, 128>>>();
    cudaStreamWaitEvent(0, eq, 0);
    retrieve_kernel<<<NCHUNK, 256, SMEM_R>>>(gamma);
    gemm_tc<2><<<dim3(DIMq/128, (Bq*Lq)/128), 256, SMEM_GEMM>>>(p_comb, p_wcT, out, nullptr, Hq*DHq);

    cudaStreamCaptureStatus cap = cudaStreamCaptureStatusNone;
    cudaStreamIsCapturing(0, &cap);
    if (cap == cudaStreamCaptureStatusNone){
        cudaStreamDestroy(s1); cudaStreamDestroy(s2);
        cudaEventDestroy(e0); cudaEventDestroy(et); cudaEventDestroy(en);
        cudaEventDestroy(eq); cudaEventDestroy(em);
    }
}